// round 5
// baseline (speedup 1.0000x reference)
#include <cuda_runtime.h>

#define HID   32
#define INDIM 128
#define NMAX  100000
#define EMAX  1600000
#define NT    256

// ---------------- static device scratch (no allocations allowed) ----------------
// All state is either recomputed each call or reset by the tail stage, so each
// launch (graph replay) sees identical initial state. Statics start zeroed.
__device__ float         g_deg [NMAX];   // neighbor count EXCLUDING self-loop; reset to 0 in tail
__device__ float         g_dinv[NMAX];
__device__ unsigned char g_m0[NMAX], g_m1[NMAX], g_m2[NMAX];   // reset in tail via lists
__device__ int           g_list0[NMAX], g_list1[NMAX], g_list2[NMAX];
__device__ int2          g_L1[EMAX], g_L2[EMAX], g_L3[EMAX];
__device__ int           g_c0, g_c1, g_c2, g_cL1, g_cL2, g_cL3;  // reset in tail
__device__ float         g_y0[(size_t)NMAX * HID];
__device__ float         g_y1[(size_t)NMAX * HID];
__device__ float         g_y2[(size_t)NMAX * HID];
__device__ float         g_a1[(size_t)NMAX * HID];   // rows zeroed per call for frontier nodes
__device__ float         g_a2[(size_t)NMAX * HID];
__device__ float         g_a3[2 * HID];              // reset in tail
__device__ int           g_bar_cnt;                  // returns to 0 after each barrier
__device__ unsigned int  g_bar_gen;                  // monotonic across calls (relative reads)

// ---------------- software grid barrier (all blocks co-resident: 1 block/SM) ---
__device__ __forceinline__ void grid_sync() {
    __threadfence();
    __syncthreads();
    if (threadIdx.x == 0) {
        unsigned int g = atomicAdd(&g_bar_gen, 0u);   // read BEFORE arriving
        if (atomicAdd(&g_bar_cnt, 1) == (int)gridDim.x - 1) {
            atomicExch(&g_bar_cnt, 0);                // atomic-ordered reset
            __threadfence();
            atomicAdd(&g_bar_gen, 1u);
        } else {
            while (atomicAdd(&g_bar_gen, 0u) == g) __nanosleep(64);
        }
    }
    __syncthreads();
    __threadfence();
}

// ---------------- edge scan: pred(dst) -> mark mOut[src], append (src,dst) ----
template<bool USE_MASK>
__device__ __forceinline__ void scan_phase(const void* ei, int i64, int E, int gt, int gs,
                                           const unsigned char* __restrict__ mIn,
                                           unsigned char* __restrict__ mOut,
                                           int2* __restrict__ L, int* __restrict__ cnt) {
    if (i64) {
        const long long* dst = (const long long*)ei + E;
        const long long* src = (const long long*)ei;
        #pragma unroll 8
        for (int e = gt; e < E; e += gs) {
            int d = (int)dst[e];
            bool hit = USE_MASK ? (__ldcg(&mIn[d]) != 0) : (d < 2);
            if (hit) {
                int s = (int)src[e];
                mOut[s] = 1;
                L[atomicAdd(cnt, 1)] = make_int2(s, d);
            }
        }
    } else {
        const int* dst = (const int*)ei + E;
        const int* src = (const int*)ei;
        #pragma unroll 8
        for (int e = gt; e < E; e += gs) {
            int d = dst[e];
            bool hit = USE_MASK ? (__ldcg(&mIn[d]) != 0) : (d < 2);
            if (hit) {
                int s = src[e];
                mOut[s] = 1;
                L[atomicAdd(cnt, 1)] = make_int2(s, d);
            }
        }
    }
}

// ---------------- node pass: compact mask -> list, copy mask, zero acc rows ---
__device__ __forceinline__ void node_phase(int N, int gt, int gs,
                                           const unsigned char* __restrict__ mIn,
                                           unsigned char* __restrict__ mOut,
                                           int* __restrict__ list, int* __restrict__ cnt,
                                           float* __restrict__ Azero) {
    for (int n = gt; n < N; n += gs) {
        unsigned char m = __ldcg(&mIn[n]);
        if (mOut) mOut[n] = m;
        if (m) {
            list[atomicAdd(cnt, 1)] = n;
            if (Azero) {
                float4* a = (float4*)(Azero + (size_t)n * HID);
                float4 z = make_float4(0.f, 0.f, 0.f, 0.f);
                #pragma unroll
                for (int j = 0; j < 8; j++) a[j] = z;
            }
        }
    }
}

// ---------------- edge aggregation: A[dst] += dinv[s]*dinv[d]*Y[src] ----------
__device__ __forceinline__ void agg_edges(const int2* __restrict__ L, int cnt,
                                          const float* __restrict__ Y, float* __restrict__ A,
                                          int warp, int nwarps, int lane) {
    for (int i = warp; i < cnt; i += nwarps) {
        int2 ed = __ldcg(&L[i]);
        float w = __ldcg(&g_dinv[ed.x]) * __ldcg(&g_dinv[ed.y]);
        atomicAdd(&A[(size_t)ed.y * HID + lane], w * __ldcg(&Y[(size_t)ed.x * HID + lane]));
    }
}

// -------- node update: h = relu(A + dinv^2*Yin + b); Yout = h @ W (32x32) -----
__device__ __forceinline__ void layer_nodes(const int* __restrict__ list, int cnt,
                                            const float* __restrict__ A,
                                            const float* __restrict__ Yin,
                                            const float* __restrict__ b,
                                            const float* __restrict__ W,
                                            float* __restrict__ Yout,
                                            int warp, int nwarps, int lane) {
    for (int i = warp; i < cnt; i += nwarps) {
        int n = __ldcg(&list[i]);
        float dv = __ldcg(&g_dinv[n]);
        float h = __ldcg(&A[(size_t)n * HID + lane])
                + dv * dv * __ldcg(&Yin[(size_t)n * HID + lane]) + b[lane];
        h = fmaxf(h, 0.f);
        float acc = 0.f;
        #pragma unroll
        for (int k = 0; k < HID; k++)
            acc = fmaf(__shfl_sync(0xffffffffu, h, k), W[k * HID + lane], acc);
        Yout[(size_t)n * HID + lane] = acc;
    }
}

// ---------------- the whole GCN in one persistent kernel ----------------------
__global__ void __launch_bounds__(NT, 1)
gcn_fused(const float* __restrict__ x, const void* __restrict__ ei, int E, int N,
          const float* __restrict__ W1, const float* __restrict__ b1,
          const float* __restrict__ W2, const float* __restrict__ b2,
          const float* __restrict__ W3, const float* __restrict__ b3,
          const float* __restrict__ Wfc, const float* __restrict__ bfc,
          float* __restrict__ out)
{
    const int tid    = threadIdx.x;
    const int gt     = blockIdx.x * NT + tid;
    const int gs     = gridDim.x * NT;
    const int warp   = gt >> 5;
    const int lane   = tid & 31;
    const int nwarps = gs >> 5;

    // int64 vs int32 edge_index detection (high words all zero => int64)
    __shared__ int s_i64;
    if (tid == 0) {
        const unsigned int* w = (const unsigned int*)ei;
        int lim = (2 * E < 512) ? 2 * E : 512;
        int is64 = 1;
        for (int k = 1; k < lim; k += 2)
            if (w[k]) { is64 = 0; break; }
        s_i64 = is64;
    }
    __syncthreads();
    const int i64 = s_i64;

    // ---- P1: seed m2 with {0,1}; scan edges with dst<2 -> L3, mark m2[src] ----
    if (gt == 0) { g_m2[0] = 1; g_m2[1] = 1; }
    scan_phase<false>(ei, i64, E, gt, gs, nullptr, g_m2, g_L3, &g_cL3);
    grid_sync();

    // ---- P2: list2 from m2, m1 = m2, zero a2 rows ----
    node_phase(N, gt, gs, g_m2, g_m1, g_list2, &g_c2, g_a2);
    grid_sync();

    // ---- P3: edges into F2 -> L2, mark m1[src] ----
    scan_phase<true>(ei, i64, E, gt, gs, g_m2, g_m1, g_L2, &g_cL2);
    grid_sync();

    // ---- P4: list1 from m1, m0 = m1, zero a1 rows ----
    node_phase(N, gt, gs, g_m1, g_m0, g_list1, &g_c1, g_a1);
    grid_sync();

    // ---- P5: edges into F1 -> L1, mark m0[src] ----
    scan_phase<true>(ei, i64, E, gt, gs, g_m1, g_m0, g_L1, &g_cL1);
    grid_sync();

    // ---- P6: degree counts for F0 dsts only + build list0 ----
    if (i64) {
        const long long* dst = (const long long*)ei + E;
        #pragma unroll 8
        for (int e = gt; e < E; e += gs) {
            int d = (int)dst[e];
            if (__ldcg(&g_m0[d])) atomicAdd(&g_deg[d], 1.0f);
        }
    } else {
        const int* dst = (const int*)ei + E;
        #pragma unroll 8
        for (int e = gt; e < E; e += gs) {
            int d = dst[e];
            if (__ldcg(&g_m0[d])) atomicAdd(&g_deg[d], 1.0f);
        }
    }
    node_phase(N, gt, gs, g_m0, nullptr, g_list0, &g_c0, nullptr);
    grid_sync();

    // ---- P7: dinv + y0 = x @ W1 for F0 nodes (warp per node) ----
    {
        int cnt = __ldcg(&g_c0);
        for (int i = warp; i < cnt; i += nwarps) {
            int n = __ldcg(&g_list0[i]);
            if (lane == 0) g_dinv[n] = rsqrtf(__ldcg(&g_deg[n]) + 1.0f);
            const float* xr = x + (size_t)n * INDIM;
            float xv0 = xr[lane], xv1 = xr[lane + 32], xv2 = xr[lane + 64], xv3 = xr[lane + 96];
            float acc = 0.f;
            #pragma unroll
            for (int k = 0; k < 32; k++)
                acc = fmaf(__shfl_sync(0xffffffffu, xv0, k), W1[(k      ) * HID + lane], acc);
            #pragma unroll
            for (int k = 0; k < 32; k++)
                acc = fmaf(__shfl_sync(0xffffffffu, xv1, k), W1[(k +  32) * HID + lane], acc);
            #pragma unroll
            for (int k = 0; k < 32; k++)
                acc = fmaf(__shfl_sync(0xffffffffu, xv2, k), W1[(k +  64) * HID + lane], acc);
            #pragma unroll
            for (int k = 0; k < 32; k++)
                acc = fmaf(__shfl_sync(0xffffffffu, xv3, k), W1[(k +  96) * HID + lane], acc);
            g_y0[(size_t)n * HID + lane] = acc;
        }
    }
    grid_sync();

    // ---- P8: aggregate layer-1 messages over L1 ----
    agg_edges(g_L1, __ldcg(&g_cL1), g_y0, g_a1, warp, nwarps, lane);
    grid_sync();

    // ---- P9: layer-1 node update -> y1 (includes @W2) ----
    layer_nodes(g_list1, __ldcg(&g_c1), g_a1, g_y0, b1, W2, g_y1, warp, nwarps, lane);
    grid_sync();

    // ================= tail: tiny remaining work, block 0 only =================
    if (blockIdx.x != 0) return;
    const int bwarp = tid >> 5;               // 0..7
    const int bw    = NT / 32;

    // agg2 over L2 (~hundreds of edges)
    agg_edges(g_L2, __ldcg(&g_cL2), g_y1, g_a2, bwarp, bw, lane);
    __threadfence(); __syncthreads();

    // layer-2 node update -> y2 (includes @W3)
    layer_nodes(g_list2, __ldcg(&g_c2), g_a2, g_y1, b2, W3, g_y2, bwarp, bw, lane);
    __threadfence(); __syncthreads();

    // agg3 over L3 (edges into nodes 0,1)
    agg_edges(g_L3, __ldcg(&g_cL3), g_y2, g_a3, bwarp, bw, lane);
    __threadfence(); __syncthreads();

    // final: h3 at {0,1}; z = concat(h3[0], h3[1]); out = z @ Wfc + bfc
    __shared__ float z[2 * HID];
    if (tid < 2 * HID) {
        int node = tid >> 5;
        float dv = __ldcg(&g_dinv[node]);
        float h = __ldcg(&g_a3[tid])
                + dv * dv * __ldcg(&g_y2[(size_t)node * HID + lane]) + b3[lane];
        z[tid] = fmaxf(h, 0.f);
    }
    __syncthreads();
    if (tid < 64) {
        float acc = bfc[tid];
        #pragma unroll
        for (int i = 0; i < 2 * HID; i++)
            acc = fmaf(z[i], Wfc[i * 64 + tid], acc);
        out[tid] = acc;
    }
    __syncthreads();

    // ---- reset touched state so the next launch (graph replay) starts clean ----
    int c0 = __ldcg(&g_c0), c1 = __ldcg(&g_c1), c2 = __ldcg(&g_c2);
    __syncthreads();
    for (int i = tid; i < c0; i += NT) { int n = __ldcg(&g_list0[i]); g_m0[n] = 0; g_deg[n] = 0.f; }
    for (int i = tid; i < c1; i += NT) { int n = __ldcg(&g_list1[i]); g_m1[n] = 0; }
    for (int i = tid; i < c2; i += NT) { int n = __ldcg(&g_list2[i]); g_m2[n] = 0; }
    if (tid < 2 * HID) g_a3[tid] = 0.f;
    if (tid == 0) { g_c0 = 0; g_c1 = 0; g_c2 = 0; g_cL1 = 0; g_cL2 = 0; g_cL3 = 0; }
    // launch boundary orders these writes before the next replay
}

// ---------------- launcher: ONE kernel ----------------------------------------
extern "C" void kernel_launch(void* const* d_in, const int* in_sizes, int n_in,
                              void* d_out, int out_size) {
    const float* x   = (const float*)d_in[0];
    const void*  ei  = d_in[1];               // int64 or int32, auto-detected
    const float* W1  = (const float*)d_in[2];
    const float* b1  = (const float*)d_in[3];
    const float* W2  = (const float*)d_in[4];
    const float* b2  = (const float*)d_in[5];
    const float* W3  = (const float*)d_in[6];
    const float* b3  = (const float*)d_in[7];
    const float* Wfc = (const float*)d_in[8];
    const float* bfc = (const float*)d_in[9];
    float* out = (float*)d_out;

    int N = in_sizes[0] / INDIM;
    int E = in_sizes[1] / 2;

    int dev = 0, sm = 0;
    cudaGetDevice(&dev);
    cudaDeviceGetAttribute(&sm, cudaDevAttrMultiProcessorCount, dev);
    int nb = (sm > 0 && sm < 148) ? sm : 148;   // 1 block/SM -> all co-resident

    gcn_fused<<<nb, NT>>>(x, ei, E, N, W1, b1, W2, b2, W3, b3, Wfc, bfc, out);
}

// round 7
// speedup vs baseline: 1.5446x; 1.5446x over previous
#include <cuda_runtime.h>

#define HID   32
#define INDIM 128
#define NMAX  100000
#define EMAX  1600000
#define NT    1024
#define BMW_MAX ((NMAX + 31) / 32)   // 3125 bitmap words

// ---------------- static device scratch (no allocations allowed) ----------------
// All mutable state is reset by the tail stage each call, so every launch
// (graph replay) sees identical initial state. Statics start zeroed.
__device__ float        g_deg [NMAX];        // reset (F0 entries) in tail
__device__ float        g_dinv[NMAX];        // recomputed for F0 each call
__device__ unsigned int g_bm0[BMW_MAX], g_bm1[BMW_MAX], g_bm2[BMW_MAX]; // reset in tail
__device__ int          g_list0[NMAX], g_list1[NMAX], g_list2[NMAX];
__device__ int2         g_L1[EMAX], g_L2[EMAX], g_L3[EMAX];
__device__ int          g_c0, g_c1, g_c2, g_cL1, g_cL2, g_cL3;          // reset in tail
__device__ float        g_y0[(size_t)NMAX * HID];
__device__ float        g_y1[(size_t)NMAX * HID];
__device__ float        g_y2[(size_t)NMAX * HID];
__device__ float        g_a1[(size_t)NMAX * HID];  // frontier rows zeroed per call
__device__ float        g_a2[(size_t)NMAX * HID];
__device__ float        g_a3[2 * HID];             // reset in tail
__device__ int          g_bar_cnt;
__device__ unsigned int g_bar_gen;                 // monotonic; compared relatively

// ---------------- software grid barrier (1 block/SM, all co-resident) ----------
__device__ __forceinline__ void grid_sync() {
    __threadfence();
    __syncthreads();
    if (threadIdx.x == 0) {
        unsigned int g = atomicAdd(&g_bar_gen, 0u);     // read BEFORE arriving
        if (atomicAdd(&g_bar_cnt, 1) == (int)gridDim.x - 1) {
            atomicExch(&g_bar_cnt, 0);
            __threadfence();
            atomicAdd(&g_bar_gen, 1u);
        } else {
            while (atomicAdd(&g_bar_gen, 0u) == g) __nanosleep(32);
        }
    }
    __syncthreads();
    __threadfence();
}

// ------- edge scan: test(dst) via smem bitmap -> mark bmOut[src], append edge --
// Loads are batched 8-deep into registers before any conditional work (MLP=8).
template<bool USE_BM>
__device__ __forceinline__ void scan_edges(const int* __restrict__ p32, int st, int E,
                                           int gt, int gs,
                                           const unsigned int* __restrict__ s_bm,
                                           unsigned int* __restrict__ bmOut,
                                           int2* __restrict__ L, int* __restrict__ cnt) {
    const int* __restrict__ dstp = p32 + (size_t)st * E;
    int e = gt;
    for (; e + 7 * gs < E; e += 8 * gs) {
        int d[8];
        #pragma unroll
        for (int j = 0; j < 8; j++) d[j] = dstp[(size_t)st * (e + j * gs)];
        #pragma unroll
        for (int j = 0; j < 8; j++) {
            bool hit = USE_BM ? ((s_bm[d[j] >> 5] >> (d[j] & 31)) & 1u) : (d[j] < 2);
            if (hit) {
                int s = p32[(size_t)st * (e + j * gs)];
                atomicOr(&bmOut[s >> 5], 1u << (s & 31));
                L[atomicAdd(cnt, 1)] = make_int2(s, d[j]);
            }
        }
    }
    for (; e < E; e += gs) {
        int d = dstp[(size_t)st * e];
        bool hit = USE_BM ? ((s_bm[d >> 5] >> (d & 31)) & 1u) : (d < 2);
        if (hit) {
            int s = p32[(size_t)st * e];
            atomicOr(&bmOut[s >> 5], 1u << (s & 31));
            L[atomicAdd(cnt, 1)] = make_int2(s, d);
        }
    }
}

// ------- node compaction from bitmap words; optional copy + acc-row zeroing ----
__device__ __forceinline__ void compact_nodes(int bmw, int gt, int gs,
                                              const unsigned int* __restrict__ bmIn,
                                              unsigned int* __restrict__ bmCopy,
                                              int* __restrict__ list, int* __restrict__ cnt,
                                              float* __restrict__ Azero) {
    for (int w = gt; w < bmw; w += gs) {
        unsigned int bits = __ldcg(&bmIn[w]);
        if (bmCopy) bmCopy[w] = bits;
        while (bits) {
            int b = __ffs(bits) - 1;
            bits &= bits - 1;
            int n = w * 32 + b;
            list[atomicAdd(cnt, 1)] = n;
            if (Azero) {
                float4* a = (float4*)(Azero + (size_t)n * HID);
                float4 z = make_float4(0.f, 0.f, 0.f, 0.f);
                #pragma unroll
                for (int j = 0; j < 8; j++) a[j] = z;
            }
        }
    }
}

// ---------------- edge aggregation: A[dst] += dinv[s]*dinv[d]*Y[src] -----------
__device__ __forceinline__ void agg_edges(const int2* __restrict__ L, int cnt,
                                          const float* __restrict__ Y, float* __restrict__ A,
                                          int warp, int nwarps, int lane) {
    for (int i = warp; i < cnt; i += nwarps) {
        int2 ed;
        float w = 0.f;
        if (lane == 0) {
            ed = __ldcg(&L[i]);
            w = __ldcg(&g_dinv[ed.x]) * __ldcg(&g_dinv[ed.y]);
        }
        ed.x = __shfl_sync(0xffffffffu, ed.x, 0);
        ed.y = __shfl_sync(0xffffffffu, ed.y, 0);
        w    = __shfl_sync(0xffffffffu, w, 0);
        atomicAdd(&A[(size_t)ed.y * HID + lane], w * __ldcg(&Y[(size_t)ed.x * HID + lane]));
    }
}

// ------- node update: h = relu(A + dinv^2*Yin + b); Yout = h @ W (32x32) -------
__device__ __forceinline__ void layer_nodes(const int* __restrict__ list, int cnt,
                                            const float* __restrict__ A,
                                            const float* __restrict__ Yin,
                                            const float* __restrict__ b,
                                            const float* __restrict__ W,
                                            float* __restrict__ Yout,
                                            int warp, int nwarps, int lane) {
    for (int i = warp; i < cnt; i += nwarps) {
        int n;
        float dv = 0.f;
        if (lane == 0) { n = __ldcg(&list[i]); dv = __ldcg(&g_dinv[n]); }
        n  = __shfl_sync(0xffffffffu, n, 0);
        dv = __shfl_sync(0xffffffffu, dv, 0);
        float h = __ldcg(&A[(size_t)n * HID + lane])
                + dv * dv * __ldcg(&Yin[(size_t)n * HID + lane]) + b[lane];
        h = fmaxf(h, 0.f);
        float acc = 0.f;
        #pragma unroll
        for (int k = 0; k < HID; k++)
            acc = fmaf(__shfl_sync(0xffffffffu, h, k), W[k * HID + lane], acc);
        Yout[(size_t)n * HID + lane] = acc;
    }
}

// ---------------- the whole GCN in one persistent kernel -----------------------
__global__ void __launch_bounds__(NT, 1)
gcn_fused(const float* __restrict__ x, const void* __restrict__ ei, int E, int N,
          const float* __restrict__ W1, const float* __restrict__ b1,
          const float* __restrict__ W2, const float* __restrict__ b2,
          const float* __restrict__ W3, const float* __restrict__ b3,
          const float* __restrict__ Wfc, const float* __restrict__ bfc,
          float* __restrict__ out)
{
    __shared__ unsigned int s_bm[BMW_MAX];
    __shared__ float        s_z[2 * HID];
    __shared__ int          s_i64;

    const int tid    = threadIdx.x;
    const int gt     = blockIdx.x * NT + tid;
    const int gs     = gridDim.x * NT;
    const int warp   = gt >> 5;
    const int lane   = tid & 31;
    const int nwarps = gs >> 5;
    const int bmw    = (N + 31) / 32;

    // int64 vs int32 edge_index detection (high words all zero => int64)
    if (tid == 0) {
        const unsigned int* w = (const unsigned int*)ei;
        int lim = (2 * E < 512) ? 2 * E : 512;
        int is64 = 1;
        for (int k = 1; k < lim; k += 2)
            if (w[k]) { is64 = 0; break; }
        s_i64 = is64;
    }
    __syncthreads();
    const int st = s_i64 ? 2 : 1;                 // int stride per element
    const int* p32 = (const int*)ei;              // low-word view

    // ---- P1: seed bm2 with {0,1}; scan dst<2 -> L3, mark bm2[src] ----
    if (gt == 0) atomicOr(&g_bm2[0], 3u);
    scan_edges<false>(p32, st, E, gt, gs, nullptr, g_bm2, g_L3, &g_cL3);
    grid_sync();

    // ---- P2: compact bm2 -> list2, bm1 = bm2, zero a2 rows ----
    compact_nodes(bmw, gt, gs, g_bm2, g_bm1, g_list2, &g_c2, g_a2);
    grid_sync();

    // ---- P3: edges into F2 -> L2, mark bm1[src] ----
    for (int w = tid; w < bmw; w += NT) s_bm[w] = __ldcg(&g_bm2[w]);
    __syncthreads();
    scan_edges<true>(p32, st, E, gt, gs, s_bm, g_bm1, g_L2, &g_cL2);
    grid_sync();

    // ---- P4: compact bm1 -> list1, bm0 = bm1, zero a1 rows ----
    compact_nodes(bmw, gt, gs, g_bm1, g_bm0, g_list1, &g_c1, g_a1);
    grid_sync();

    // ---- P5: edges into F1 -> L1, mark bm0[src] ----
    for (int w = tid; w < bmw; w += NT) s_bm[w] = __ldcg(&g_bm1[w]);
    __syncthreads();
    scan_edges<true>(p32, st, E, gt, gs, s_bm, g_bm0, g_L1, &g_cL1);
    grid_sync();

    // ---- P6: degree counts for F0 dsts + compact bm0 -> list0 ----
    for (int w = tid; w < bmw; w += NT) s_bm[w] = __ldcg(&g_bm0[w]);
    __syncthreads();
    {
        const int* __restrict__ dstp = p32 + (size_t)st * E;
        int e = gt;
        for (; e + 7 * gs < E; e += 8 * gs) {
            int d[8];
            #pragma unroll
            for (int j = 0; j < 8; j++) d[j] = dstp[(size_t)st * (e + j * gs)];
            #pragma unroll
            for (int j = 0; j < 8; j++)
                if ((s_bm[d[j] >> 5] >> (d[j] & 31)) & 1u)
                    atomicAdd(&g_deg[d[j]], 1.0f);
        }
        for (; e < E; e += gs) {
            int d = dstp[(size_t)st * e];
            if ((s_bm[d >> 5] >> (d & 31)) & 1u)
                atomicAdd(&g_deg[d], 1.0f);
        }
    }
    compact_nodes(bmw, gt, gs, g_bm0, nullptr, g_list0, &g_c0, nullptr);
    grid_sync();

    // ---- P7: dinv + y0 = x @ W1 for F0 nodes (warp per node) ----
    {
        int cnt = __ldcg(&g_c0);
        for (int i = warp; i < cnt; i += nwarps) {
            int n = __ldcg(&g_list0[i]);
            if (lane == 0) g_dinv[n] = rsqrtf(__ldcg(&g_deg[n]) + 1.0f);   // +1 self-loop
            const float* xr = x + (size_t)n * INDIM;
            float xv0 = xr[lane], xv1 = xr[lane + 32], xv2 = xr[lane + 64], xv3 = xr[lane + 96];
            float acc = 0.f;
            #pragma unroll
            for (int k = 0; k < 32; k++)
                acc = fmaf(__shfl_sync(0xffffffffu, xv0, k), W1[(k      ) * HID + lane], acc);
            #pragma unroll
            for (int k = 0; k < 32; k++)
                acc = fmaf(__shfl_sync(0xffffffffu, xv1, k), W1[(k +  32) * HID + lane], acc);
            #pragma unroll
            for (int k = 0; k < 32; k++)
                acc = fmaf(__shfl_sync(0xffffffffu, xv2, k), W1[(k +  64) * HID + lane], acc);
            #pragma unroll
            for (int k = 0; k < 32; k++)
                acc = fmaf(__shfl_sync(0xffffffffu, xv3, k), W1[(k +  96) * HID + lane], acc);
            g_y0[(size_t)n * HID + lane] = acc;
        }
    }
    grid_sync();

    // ---- P8: aggregate layer-1 messages over L1 (grid-wide) ----
    agg_edges(g_L1, __ldcg(&g_cL1), g_y0, g_a1, warp, nwarps, lane);
    grid_sync();

    // ================= tail: tiny remaining work, block 0 only =================
    if (blockIdx.x != 0) return;
    const int bwarp = tid >> 5;               // 0..31
    const int bw    = NT / 32;

    // layer-1 node update -> y1 (includes @W2);  |F1| ~ hundreds
    layer_nodes(g_list1, __ldcg(&g_c1), g_a1, g_y0, b1, W2, g_y1, bwarp, bw, lane);
    __threadfence(); __syncthreads();

    // agg2 over L2 (~hundreds of edges)
    agg_edges(g_L2, __ldcg(&g_cL2), g_y1, g_a2, bwarp, bw, lane);
    __threadfence(); __syncthreads();

    // layer-2 node update -> y2 (includes @W3);  |F2| ~ tens
    layer_nodes(g_list2, __ldcg(&g_c2), g_a2, g_y1, b2, W3, g_y2, bwarp, bw, lane);
    __threadfence(); __syncthreads();

    // agg3 over L3 (edges into nodes 0,1)
    agg_edges(g_L3, __ldcg(&g_cL3), g_y2, g_a3, bwarp, bw, lane);
    __threadfence(); __syncthreads();

    // final: h3 at {0,1}; z = concat(h3[0], h3[1]); out = z @ Wfc + bfc
    if (tid < 2 * HID) {
        int node = tid >> 5;
        float dv = __ldcg(&g_dinv[node]);
        float h = __ldcg(&g_a3[tid])
                + dv * dv * __ldcg(&g_y2[(size_t)node * HID + lane]) + b3[lane];
        s_z[tid] = fmaxf(h, 0.f);
    }
    __syncthreads();
    if (tid < 64) {
        float acc = bfc[tid];
        #pragma unroll
        for (int i = 0; i < 2 * HID; i++)
            acc = fmaf(s_z[i], Wfc[i * 64 + tid], acc);
        out[tid] = acc;
    }
    __syncthreads();

    // ---- reset touched state so the next launch (graph replay) starts clean ---
    int c0 = __ldcg(&g_c0);
    __syncthreads();
    for (int i = tid; i < c0; i += NT) { int n = __ldcg(&g_list0[i]); g_deg[n] = 0.f; }
    for (int w = tid; w < bmw; w += NT) { g_bm0[w] = 0u; g_bm1[w] = 0u; g_bm2[w] = 0u; }
    if (tid < 2 * HID) g_a3[tid] = 0.f;
    if (tid == 0) { g_c0 = 0; g_c1 = 0; g_c2 = 0; g_cL1 = 0; g_cL2 = 0; g_cL3 = 0; }
    // launch boundary orders these writes before the next replay
}

// ---------------- launcher: ONE kernel -----------------------------------------
extern "C" void kernel_launch(void* const* d_in, const int* in_sizes, int n_in,
                              void* d_out, int out_size) {
    const float* x   = (const float*)d_in[0];
    const void*  ei  = d_in[1];               // int64 or int32, auto-detected
    const float* W1  = (const float*)d_in[2];
    const float* b1  = (const float*)d_in[3];
    const float* W2  = (const float*)d_in[4];
    const float* b2  = (const float*)d_in[5];
    const float* W3  = (const float*)d_in[6];
    const float* b3  = (const float*)d_in[7];
    const float* Wfc = (const float*)d_in[8];
    const float* bfc = (const float*)d_in[9];
    float* out = (float*)d_out;

    int N = in_sizes[0] / INDIM;
    int E = in_sizes[1] / 2;

    int dev = 0, sm = 0;
    cudaGetDevice(&dev);
    cudaDeviceGetAttribute(&sm, cudaDevAttrMultiProcessorCount, dev);
    if (sm <= 0) sm = 64;                     // conservative fallback, still co-resident

    gcn_fused<<<sm, NT>>>(x, ei, E, N, W1, b1, W2, b2, W3, b3, Wfc, bfc, out);
}

// round 8
// speedup vs baseline: 2.3550x; 1.5247x over previous
#include <cuda_runtime.h>

#define HID   32
#define INDIM 128
#define NMAX  100000
#define EMAX  1600000
#define NT    1024
#define BMW_MAX ((NMAX + 31) / 32)   // 3125 bitmap words

// ---------------- static device scratch (no allocations allowed) ----------------
// All mutable state is reset within the same launch, so every graph replay sees
// identical initial state. Statics start zeroed.
__device__ float        g_deg [NMAX];              // reset grid-wide in P5
__device__ float        g_dinv[NMAX];              // recomputed for F0 each call
__device__ unsigned int g_bm0[BMW_MAX], g_bm1[BMW_MAX], g_bm2[BMW_MAX]; // reset in P5
__device__ int          g_list0[NMAX], g_list1[NMAX], g_list2[NMAX];
__device__ int2         g_L1[EMAX], g_L2[EMAX], g_L3[EMAX];
__device__ int          g_c0, g_c1, g_c2, g_cL1, g_cL2, g_cL3;          // reset in tail
__device__ float        g_y0[(size_t)NMAX * HID];
__device__ float        g_y1[(size_t)NMAX * HID];
__device__ float        g_y2[(size_t)NMAX * HID];
__device__ float        g_a1[(size_t)NMAX * HID];  // frontier rows zeroed on insert
__device__ float        g_a2[(size_t)NMAX * HID];
__device__ float        g_a3[2 * HID];             // reset in tail
__device__ int          g_bar_cnt;                 // returns to 0 each barrier
__device__ volatile unsigned int g_bar_gen;        // monotonic; compared relatively

// ------------- software grid barrier: LOAD-polling (no atomic spin) ------------
__device__ __forceinline__ void grid_sync() {
    __syncthreads();
    if (threadIdx.x == 0) {
        __threadfence();                           // publish this block's writes
        unsigned int g = g_bar_gen;                // volatile read (L2)
        if (atomicAdd(&g_bar_cnt, 1) == (int)gridDim.x - 1) {
            g_bar_cnt = 0;                         // safe: all others spin on gen
            __threadfence();
            g_bar_gen = g + 1;                     // volatile release store
        } else {
            while (g_bar_gen == g) { }             // plain L2 load spin, broadcast-friendly
        }
    }
    __syncthreads();
}

// ---------------- frontier insertion with atomicOr dedupe + cascade ------------
__device__ __forceinline__ void add_f0(int n) {
    unsigned int b = 1u << (n & 31);
    if (!(atomicOr(&g_bm0[n >> 5], b) & b))
        g_list0[atomicAdd(&g_c0, 1)] = n;
}
__device__ __forceinline__ void add_f1(int n) {
    unsigned int b = 1u << (n & 31);
    if (!(atomicOr(&g_bm1[n >> 5], b) & b)) {
        g_list1[atomicAdd(&g_c1, 1)] = n;
        float4* a = (float4*)(g_a1 + (size_t)n * HID);
        float4 z = make_float4(0.f, 0.f, 0.f, 0.f);
        #pragma unroll
        for (int j = 0; j < 8; j++) a[j] = z;
        add_f0(n);
    }
}
__device__ __forceinline__ void add_f2(int n) {
    unsigned int b = 1u << (n & 31);
    if (!(atomicOr(&g_bm2[n >> 5], b) & b)) {
        g_list2[atomicAdd(&g_c2, 1)] = n;
        float4* a = (float4*)(g_a2 + (size_t)n * HID);
        float4 z = make_float4(0.f, 0.f, 0.f, 0.f);
        #pragma unroll
        for (int j = 0; j < 8; j++) a[j] = z;
        add_f1(n);
    }
}

// ---- masked edge scan (smem bitmap): append (s,d) to L, cascade s at LVL ------
template<int LVL>   // 1: cascade into F1 (and F0); 0: cascade into F0 only
__device__ __forceinline__ void scan_masked(const int* __restrict__ p32, int st, int E,
                                            int gt, int gs,
                                            const unsigned int* __restrict__ s_bm,
                                            int2* __restrict__ L, int* __restrict__ cnt) {
    const int* __restrict__ dstp = p32 + (size_t)st * E;
    int e = gt;
    for (; e + 7 * gs < E; e += 8 * gs) {
        int d[8];
        #pragma unroll
        for (int j = 0; j < 8; j++) d[j] = dstp[(size_t)st * (e + j * gs)];
        #pragma unroll
        for (int j = 0; j < 8; j++) {
            if ((s_bm[d[j] >> 5] >> (d[j] & 31)) & 1u) {
                int s = p32[(size_t)st * (e + j * gs)];
                L[atomicAdd(cnt, 1)] = make_int2(s, d[j]);
                if (LVL == 1) add_f1(s); else add_f0(s);
            }
        }
    }
    for (; e < E; e += gs) {
        int d = dstp[(size_t)st * e];
        if ((s_bm[d >> 5] >> (d & 31)) & 1u) {
            int s = p32[(size_t)st * e];
            L[atomicAdd(cnt, 1)] = make_int2(s, d);
            if (LVL == 1) add_f1(s); else add_f0(s);
        }
    }
}

// ---------------- edge aggregation: A[dst] += dinv[s]*dinv[d]*Y[src] -----------
__device__ __forceinline__ void agg_edges(const int2* __restrict__ L, int cnt,
                                          const float* __restrict__ Y, float* __restrict__ A,
                                          int warp, int nwarps, int lane) {
    for (int i = warp; i < cnt; i += nwarps) {
        int2 ed;
        float w = 0.f;
        if (lane == 0) {
            ed = __ldcg(&L[i]);
            w = __ldcg(&g_dinv[ed.x]) * __ldcg(&g_dinv[ed.y]);
        }
        ed.x = __shfl_sync(0xffffffffu, ed.x, 0);
        ed.y = __shfl_sync(0xffffffffu, ed.y, 0);
        w    = __shfl_sync(0xffffffffu, w, 0);
        atomicAdd(&A[(size_t)ed.y * HID + lane], w * __ldcg(&Y[(size_t)ed.x * HID + lane]));
    }
}

// ------- node update: h = relu(A + dinv^2*Yin + b); Yout = h @ W (32x32) -------
__device__ __forceinline__ void layer_nodes(const int* __restrict__ list, int cnt,
                                            const float* __restrict__ A,
                                            const float* __restrict__ Yin,
                                            const float* __restrict__ b,
                                            const float* __restrict__ W,
                                            float* __restrict__ Yout,
                                            int warp, int nwarps, int lane) {
    for (int i = warp; i < cnt; i += nwarps) {
        int n = 0;
        float dv = 0.f;
        if (lane == 0) { n = __ldcg(&list[i]); dv = __ldcg(&g_dinv[n]); }
        n  = __shfl_sync(0xffffffffu, n, 0);
        dv = __shfl_sync(0xffffffffu, dv, 0);
        float h = __ldcg(&A[(size_t)n * HID + lane])
                + dv * dv * __ldcg(&Yin[(size_t)n * HID + lane]) + b[lane];
        h = fmaxf(h, 0.f);
        float acc = 0.f;
        #pragma unroll
        for (int k = 0; k < HID; k++)
            acc = fmaf(__shfl_sync(0xffffffffu, h, k), W[k * HID + lane], acc);
        Yout[(size_t)n * HID + lane] = acc;
    }
}

// ---------------- the whole GCN in one persistent kernel -----------------------
__global__ void __launch_bounds__(NT, 1)
gcn_fused(const float* __restrict__ x, const void* __restrict__ ei, int E, int N,
          const float* __restrict__ W1, const float* __restrict__ b1,
          const float* __restrict__ W2, const float* __restrict__ b2,
          const float* __restrict__ W3, const float* __restrict__ b3,
          const float* __restrict__ Wfc, const float* __restrict__ bfc,
          float* __restrict__ out)
{
    __shared__ unsigned int s_bm[BMW_MAX];
    __shared__ float        s_z[2 * HID];
    __shared__ int          s_i64;

    const int tid    = threadIdx.x;
    const int gt     = blockIdx.x * NT + tid;
    const int gs     = gridDim.x * NT;
    const int warp   = gt >> 5;
    const int lane   = tid & 31;
    const int nwarps = gs >> 5;
    const int bmw    = (N + 31) / 32;

    // int64 vs int32 edge_index detection (high words all zero => int64)
    if (tid == 0) {
        const unsigned int* w = (const unsigned int*)ei;
        int lim = (2 * E < 512) ? 2 * E : 512;
        int is64 = 1;
        for (int k = 1; k < lim; k += 2)
            if (w[k]) { is64 = 0; break; }
        s_i64 = is64;
    }
    __syncthreads();
    const int st = s_i64 ? 2 : 1;                 // ints per element
    const int* p32 = (const int*)ei;              // low-word view

    // ---- P1: deg for ALL dsts; edges with dst<2 -> L3; seed+cascade F2 --------
    if (gt == 0) { add_f2(0); add_f2(1); }
    {
        const int* __restrict__ dstp = p32 + (size_t)st * E;
        int e = gt;
        for (; e + 7 * gs < E; e += 8 * gs) {
            int d[8];
            #pragma unroll
            for (int j = 0; j < 8; j++) d[j] = dstp[(size_t)st * (e + j * gs)];
            #pragma unroll
            for (int j = 0; j < 8; j++) atomicAdd(&g_deg[d[j]], 1.0f);
            #pragma unroll
            for (int j = 0; j < 8; j++) {
                if (d[j] < 2) {
                    int s = p32[(size_t)st * (e + j * gs)];
                    g_L3[atomicAdd(&g_cL3, 1)] = make_int2(s, d[j]);
                    add_f2(s);
                }
            }
        }
        for (; e < E; e += gs) {
            int d = dstp[(size_t)st * e];
            atomicAdd(&g_deg[d], 1.0f);
            if (d < 2) {
                int s = p32[(size_t)st * e];
                g_L3[atomicAdd(&g_cL3, 1)] = make_int2(s, d);
                add_f2(s);
            }
        }
    }
    grid_sync();

    // ---- P2: edges into F2 -> L2; cascade src into F1 (and F0) ----------------
    for (int w = tid; w < bmw; w += NT) s_bm[w] = __ldcg(&g_bm2[w]);
    __syncthreads();
    scan_masked<1>(p32, st, E, gt, gs, s_bm, g_L2, &g_cL2);
    grid_sync();

    // ---- P3: edges into F1 -> L1; cascade src into F0 -------------------------
    for (int w = tid; w < bmw; w += NT) s_bm[w] = __ldcg(&g_bm1[w]);
    __syncthreads();
    scan_masked<0>(p32, st, E, gt, gs, s_bm, g_L1, &g_cL1);
    grid_sync();

    // ---- P4: dinv + y0 = x @ W1 for F0 nodes (warp per node) ------------------
    {
        int cnt = __ldcg(&g_c0);
        for (int i = warp; i < cnt; i += nwarps) {
            int n = 0;
            if (lane == 0) n = __ldcg(&g_list0[i]);
            n = __shfl_sync(0xffffffffu, n, 0);
            if (lane == 0) g_dinv[n] = rsqrtf(__ldcg(&g_deg[n]) + 1.0f);  // +1 self-loop
            const float* xr = x + (size_t)n * INDIM;
            float xv0 = xr[lane], xv1 = xr[lane + 32], xv2 = xr[lane + 64], xv3 = xr[lane + 96];
            float acc = 0.f;
            #pragma unroll
            for (int k = 0; k < 32; k++)
                acc = fmaf(__shfl_sync(0xffffffffu, xv0, k), W1[(k      ) * HID + lane], acc);
            #pragma unroll
            for (int k = 0; k < 32; k++)
                acc = fmaf(__shfl_sync(0xffffffffu, xv1, k), W1[(k +  32) * HID + lane], acc);
            #pragma unroll
            for (int k = 0; k < 32; k++)
                acc = fmaf(__shfl_sync(0xffffffffu, xv2, k), W1[(k +  64) * HID + lane], acc);
            #pragma unroll
            for (int k = 0; k < 32; k++)
                acc = fmaf(__shfl_sync(0xffffffffu, xv3, k), W1[(k +  96) * HID + lane], acc);
            g_y0[(size_t)n * HID + lane] = acc;
        }
    }
    grid_sync();

    // ---- P5: agg1 over L1; overlap grid-wide reset of deg + bitmaps -----------
    for (int i = gt; i < N; i += gs) g_deg[i] = 0.f;          // dead after P4
    for (int w = gt; w < bmw; w += gs) { g_bm0[w] = 0u; g_bm1[w] = 0u; g_bm2[w] = 0u; }
    agg_edges(g_L1, __ldcg(&g_cL1), g_y0, g_a1, warp, nwarps, lane);
    grid_sync();

    // ---- P6: layer-1 node update -> y1 (includes @W2), grid-wide --------------
    layer_nodes(g_list1, __ldcg(&g_c1), g_a1, g_y0, b1, W2, g_y1, warp, nwarps, lane);
    grid_sync();

    // ---- P7: agg2 over L2, grid-wide ------------------------------------------
    agg_edges(g_L2, __ldcg(&g_cL2), g_y1, g_a2, warp, nwarps, lane);
    grid_sync();

    // ================= tail: tiny remaining work, block 0 only =================
    if (blockIdx.x != 0) return;
    const int bwarp = tid >> 5;               // 0..31
    const int bw    = NT / 32;

    // layer-2 node update -> y2 (includes @W3);  |F2| ~ tens
    layer_nodes(g_list2, __ldcg(&g_c2), g_a2, g_y1, b2, W3, g_y2, bwarp, bw, lane);
    __threadfence(); __syncthreads();

    // agg3 over L3 (edges into nodes 0,1)
    agg_edges(g_L3, __ldcg(&g_cL3), g_y2, g_a3, bwarp, bw, lane);
    __threadfence(); __syncthreads();

    // final: h3 at {0,1}; z = concat(h3[0], h3[1]); out = z @ Wfc + bfc
    if (tid < 2 * HID) {
        int node = tid >> 5;
        float dv = __ldcg(&g_dinv[node]);
        float h = __ldcg(&g_a3[tid])
                + dv * dv * __ldcg(&g_y2[(size_t)node * HID + lane]) + b3[lane];
        s_z[tid] = fmaxf(h, 0.f);
    }
    __syncthreads();
    if (tid < 64) {
        float acc = bfc[tid];
        #pragma unroll
        for (int i = 0; i < 2 * HID; i++)
            acc = fmaf(s_z[i], Wfc[i * 64 + tid], acc);
        out[tid] = acc;
    }
    __syncthreads();

    // ---- reset remaining state for the next launch (graph replay) -------------
    if (tid < 2 * HID) g_a3[tid] = 0.f;
    if (tid == 0) { g_c0 = 0; g_c1 = 0; g_c2 = 0; g_cL1 = 0; g_cL2 = 0; g_cL3 = 0; }
    // launch boundary orders these writes before the next replay
}

// ---------------- launcher: ONE kernel -----------------------------------------
extern "C" void kernel_launch(void* const* d_in, const int* in_sizes, int n_in,
                              void* d_out, int out_size) {
    const float* x   = (const float*)d_in[0];
    const void*  ei  = d_in[1];               // int64 or int32, auto-detected
    const float* W1  = (const float*)d_in[2];
    const float* b1  = (const float*)d_in[3];
    const float* W2  = (const float*)d_in[4];
    const float* b2  = (const float*)d_in[5];
    const float* W3  = (const float*)d_in[6];
    const float* b3  = (const float*)d_in[7];
    const float* Wfc = (const float*)d_in[8];
    const float* bfc = (const float*)d_in[9];
    float* out = (float*)d_out;

    int N = in_sizes[0] / INDIM;
    int E = in_sizes[1] / 2;

    int dev = 0, sm = 0;
    cudaGetDevice(&dev);
    cudaDeviceGetAttribute(&sm, cudaDevAttrMultiProcessorCount, dev);
    if (sm <= 0) sm = 64;                     // conservative fallback, still co-resident

    gcn_fused<<<sm, NT>>>(x, ei, E, N, W1, b1, W2, b2, W3, b3, Wfc, bfc, out);
}